// round 16
// baseline (speedup 1.0000x reference)
#include <cuda_runtime.h>
#include <cuda_bf16.h>
#include <math.h>
#include <stdint.h>

#define BB 4096
#define DD 512
#define QQ 16384
#define UU 256
#define OIM_SCALE 30.0f
#define C_LOG2E 43.280851226668896f   // 30 * log2(e)

// ---------------- scratch (device globals; no allocation allowed) ----------
__device__ float g_cls_sum[UU * DD];              // zeroed by k_gemm prologue
__device__ int   g_cls_cnt[UU];                   // zeroed by k_gemm prologue
__device__ int   g_unrank[UU];
__device__ float g_uniq_emb_n[UU * DD];
__device__ __nv_bfloat16 g_Abf[BB * DD];          // 4 MB (normalized inputs, bf16)
__device__ __nv_bfloat16 g_Bbf[(size_t)QQ * DD];  // 16 MB (effective queue, bf16)
__device__ unsigned char g_good[QQ];
__device__ float g_target[BB];
__device__ float g_rowsum[BB];

// ---------------- helpers ----------------------------------------------------
__device__ __forceinline__ uint32_t smem_u32(const void* p) {
    uint32_t a;
    asm("{ .reg .u64 t; cvta.to.shared.u64 t, %1; cvt.u32.u64 %0, t; }"
        : "=r"(a) : "l"(p));
    return a;
}
__device__ __forceinline__ void cpa16(uint32_t sm, const void* g) {
    asm volatile("cp.async.cg.shared.global [%0], [%1], 16;" :: "r"(sm), "l"(g));
}
__device__ __forceinline__ void cpa_commit() {
    asm volatile("cp.async.commit_group;" ::: "memory");
}
__device__ __forceinline__ void ldsm4(uint32_t* r, uint32_t addr) {
    asm volatile("ldmatrix.sync.aligned.m8n8.x4.shared.b16 {%0,%1,%2,%3}, [%4];"
                 : "=r"(r[0]), "=r"(r[1]), "=r"(r[2]), "=r"(r[3]) : "r"(addr));
}
__device__ __forceinline__ void mma16816(float* d, const uint32_t* a,
                                         const uint32_t* b) {
    asm volatile(
        "mma.sync.aligned.m16n8k16.row.col.f32.bf16.bf16.f32 "
        "{%0,%1,%2,%3}, {%4,%5,%6,%7}, {%8,%9}, {%0,%1,%2,%3};"
        : "+f"(d[0]), "+f"(d[1]), "+f"(d[2]), "+f"(d[3])
        : "r"(a[0]), "r"(a[1]), "r"(a[2]), "r"(a[3]), "r"(b[0]), "r"(b[1]));
}
#define SWZ(o) ((o) ^ (((o) >> 3) & 0x70))

__device__ __forceinline__ void pack_bf16_store(float4 v, __nv_bfloat16* dst,
                                                size_t e) {
    __nv_bfloat162 h01 = __floats2bfloat162_rn(v.x, v.y);
    __nv_bfloat162 h23 = __floats2bfloat162_rn(v.z, v.w);
    uint2 u;
    u.x = *reinterpret_cast<uint32_t*>(&h01);
    u.y = *reinterpret_cast<uint32_t*>(&h23);
    reinterpret_cast<uint2*>(dst)[e >> 2] = u;
}

// ---------------- 1: normalize rows -> bf16 A + scatter (8 rows/block) ------
__global__ void k_row(const float* __restrict__ inputs,
                      const int*   __restrict__ labels) {
    int b0 = blockIdx.x * 8;      // 512 blocks
    int t = threadIdx.x;          // 128
    float4 v[8];
    #pragma unroll
    for (int i = 0; i < 8; i++)
        v[i] = reinterpret_cast<const float4*>(inputs + (size_t)(b0 + i) * DD)[t];
    float s[8];
    #pragma unroll
    for (int i = 0; i < 8; i++)
        s[i] = v[i].x * v[i].x + v[i].y * v[i].y + v[i].z * v[i].z + v[i].w * v[i].w;
    #pragma unroll
    for (int o = 16; o; o >>= 1)
        #pragma unroll
        for (int i = 0; i < 8; i++)
            s[i] += __shfl_xor_sync(0xffffffffu, s[i], o);
    __shared__ float sh[8][4];
    if ((t & 31) == 0)
        #pragma unroll
        for (int i = 0; i < 8; i++) sh[i][t >> 5] = s[i];
    __syncthreads();
    #pragma unroll
    for (int i = 0; i < 8; i++) {
        float inv = 1.0f / fmaxf(sqrtf(sh[i][0] + sh[i][1] + sh[i][2] + sh[i][3]), 1e-12f);
        pack_bf16_store(make_float4(v[i].x * inv, v[i].y * inv, v[i].z * inv, v[i].w * inv),
                        g_Abf, (size_t)(b0 + i) * DD + t * 4);
    }
    #pragma unroll
    for (int i = 0; i < 8; i++) {
        int lab = labels[b0 + i];
        float* cs = g_cls_sum + lab * DD + t * 4;
        atomicAdd(cs + 0, v[i].x); atomicAdd(cs + 1, v[i].y);
        atomicAdd(cs + 2, v[i].z); atomicAdd(cs + 3, v[i].w);
        if (t == 0) atomicAdd(&g_cls_cnt[lab], 1);
    }
}

// ---------------- 2: class means, normalized + rank table --------------------
__global__ void k_class() {
    int u = blockIdx.x;           // 256 blocks
    int t = threadIdx.x;          // 128
    int cnt = g_cls_cnt[u];
    float invc = cnt > 0 ? 1.0f / (float)cnt : 0.0f;
    float4 v = reinterpret_cast<const float4*>(g_cls_sum + u * DD)[t];
    v.x *= invc; v.y *= invc; v.z *= invc; v.w *= invc;
    float ss = v.x * v.x + v.y * v.y + v.z * v.z + v.w * v.w;
    #pragma unroll
    for (int o = 16; o; o >>= 1) ss += __shfl_xor_sync(0xffffffffu, ss, o);
    __shared__ float sh[4];
    __shared__ int shr[4];
    int rloc = 0;
    if (t < u && g_cls_cnt[t] > 0) rloc++;
    if (t + 128 < u && g_cls_cnt[t + 128] > 0) rloc++;
    #pragma unroll
    for (int o = 16; o; o >>= 1) rloc += __shfl_xor_sync(0xffffffffu, rloc, o);
    if ((t & 31) == 0) { sh[t >> 5] = ss; shr[t >> 5] = rloc; }
    __syncthreads();
    float inv = 1.0f / fmaxf(sqrtf(sh[0] + sh[1] + sh[2] + sh[3]), 1e-12f);
    float4 vn = make_float4(v.x * inv, v.y * inv, v.z * inv, v.w * inv);
    reinterpret_cast<float4*>(g_uniq_emb_n + u * DD)[t] = vn;
    if (t == 0 && cnt > 0) {
        int r = shr[0] + shr[1] + shr[2] + shr[3];
        g_unrank[r] = u;
    }
}

// ---------------- 3: fused queue resolution (8 rows, MLP 8) + target logits --
__global__ void k_build(const float* __restrict__ emb_cq,
                        const int*   __restrict__ label_cq,
                        const int*   __restrict__ header,
                        const int*   __restrict__ labels,
                        const float* __restrict__ inputs) {
    int blk = blockIdx.x;
    int t = threadIdx.x;          // 128

    if (blk < QQ / 8) {
        int h0 = header[0];
        int q0 = blk * 8;
        const float* src[8];
        uint64_t gpack = 0;
        #pragma unroll
        for (int i = 0; i < 8; i++) {
            int q = q0 + i;
            int u = q - h0;
            u = ((u % QQ) + QQ) % QQ;
            unsigned char good;
            if (u < UU) {
                src[i] = g_uniq_emb_n + g_unrank[u] * DD;
                good = 1;
            } else {
                int lab = label_cq[q];
                bool inuniq = (lab >= 0 && lab < UU && g_cls_cnt[lab] > 0);
                good = (lab != -1 && !inuniq) ? 1 : 0;
                src[i] = emb_cq + (size_t)q * DD;
            }
            gpack |= (uint64_t)good << (8 * i);
        }
        float4 v[8];
        #pragma unroll
        for (int i = 0; i < 8; i++)
            v[i] = reinterpret_cast<const float4*>(src[i])[t];
        #pragma unroll
        for (int i = 0; i < 8; i++)
            pack_bf16_store(v[i], g_Bbf, (size_t)(q0 + i) * DD + t * 4);
        if (t == 0)
            *reinterpret_cast<uint64_t*>(g_good + q0) = gpack;
    } else {
        int b = blk - QQ / 8;
        int lab = labels[b];
        float4 a = reinterpret_cast<const float4*>(inputs + (size_t)b * DD)[t];
        float4 e = reinterpret_cast<const float4*>(g_uniq_emb_n + lab * DD)[t];
        float ss = a.x * a.x + a.y * a.y + a.z * a.z + a.w * a.w;
        float s  = a.x * e.x + a.y * e.y + a.z * e.z + a.w * e.w;
        #pragma unroll
        for (int o = 16; o; o >>= 1) {
            ss += __shfl_xor_sync(0xffffffffu, ss, o);
            s  += __shfl_xor_sync(0xffffffffu, s, o);
        }
        __shared__ float shs[4], shd[4];
        if ((t & 31) == 0) { shs[t >> 5] = ss; shd[t >> 5] = s; }
        __syncthreads();
        if (t == 0) {
            float tot_ss = shs[0] + shs[1] + shs[2] + shs[3];
            float tot_s  = shd[0] + shd[1] + shd[2] + shd[3];
            float inv = 1.0f / fmaxf(sqrtf(tot_ss), 1e-12f);
            g_target[b] = OIM_SCALE * tot_s * inv;
            g_rowsum[b] = 0.0f;
        }
    }
}

// ---------------- 4: PERSISTENT HMMA GEMM + fused masked exp row-sum ---------
// 304 CTAs (152 SMs x occ 2), each owns ~13-14 consecutive n-major tiles.
// Continuous 2-stage cp.async chunk stream across tile boundaries (fill stall
// once per strip); rowsums accumulate in registers, atomics once per
// M-segment. Compute body identical to R15. Stage parity c&1 is static under
// the unrolled 8-chunk inner loop (period aligned).
#define NCTA 304
#define NTILES ((BB / 128) * (QQ / 128))   // 4096
#define STAGES 2
#define STAGE_BYTES 32768           // (128+128) rows * 128B
#define B_OFF 16384
#define GOOD_OFF (STAGES * STAGE_BYTES)
#define SMEM_DYN (GOOD_OFF + 512 + 1024)

__global__ void __launch_bounds__(256, 2) k_gemm() {
    extern __shared__ char smraw[];
    const uint32_t sb0 = smem_u32(smraw);
    const uint32_t sbase = (sb0 + 1023) & ~1023u;
    char* smc = smraw + (sbase - sb0);
    float* goodf = (float*)(smc + GOOD_OFF);

    const int tid = threadIdx.x;
    const int lid = tid & 31;
    const int w = tid >> 5;
    const int wm = w >> 1;          // 0..3
    const int wn = w & 1;           // 0..1
    const int bid = blockIdx.x;

    // strip assignment: first `rem` CTAs take per+1 tiles
    const int per = NTILES / NCTA;              // 13
    const int rem = NTILES - per * NCTA;        // 144
    int start, cnt;
    if (bid < rem) { cnt = per + 1; start = bid * (per + 1); }
    else           { cnt = per;     start = rem * (per + 1) + (bid - rem) * per; }

    const int lrow = tid >> 3;      // 0..31
    const int lch = tid & 7;
    uint32_t soff[4];
    #pragma unroll
    for (int it = 0; it < 4; it++) {
        uint32_t o = (uint32_t)(lrow + it * 32) * 128 + lch * 16;
        soff[it] = SWZ(o);
    }

    auto load_chunk = [&](int m0, int n0, int kc, int s) {
        uint32_t sa = sbase + s * STAGE_BYTES;
        const __nv_bfloat16* gA = g_Abf + (size_t)(m0 + lrow) * DD + kc * 64 + lch * 8;
        const __nv_bfloat16* gB = g_Bbf + (size_t)(n0 + lrow) * DD + kc * 64 + lch * 8;
        #pragma unroll
        for (int it = 0; it < 4; it++) {
            cpa16(sa + soff[it], gA + (size_t)it * 32 * DD);
            cpa16(sa + B_OFF + soff[it], gB + (size_t)it * 32 * DD);
        }
        cpa_commit();
    };

    // kick pipeline: chunk 0 of the first tile, stage 0
    {
        int t0 = start;
        load_chunk((t0 >> 7) * 128, (t0 & 127) * 128, 0, 0);
    }

    // self-cleaning: reset class accumulators for the NEXT graph replay.
    if (bid < 128) {
        reinterpret_cast<float4*>(g_cls_sum)[bid * 256 + tid] =
            make_float4(0.0f, 0.0f, 0.0f, 0.0f);
        if (bid == 0) g_cls_cnt[tid] = 0;
    }

    float acc[2][8][4];
    #pragma unroll
    for (int i = 0; i < 2; i++)
        #pragma unroll
        for (int j = 0; j < 8; j++)
            #pragma unroll
            for (int k = 0; k < 4; k++) acc[i][j][k] = 0.0f;
    float rs[4] = {0.0f, 0.0f, 0.0f, 0.0f};

    const int arow = wm * 32 + (lid & 15);
    const int acolh = lid >> 4;
    const int brow = wn * 64 + ((lid >> 4) << 3) + (lid & 7);
    const int bcolh = (lid >> 3) & 1;

    for (int i = 0; i < cnt; i++) {
        const int tt = start + i;
        const int m0 = (tt >> 7) * 128;
        const int n0 = (tt & 127) * 128;
        const bool has_next = (i + 1 < cnt);
        const int nt = tt + 1;
        const int nm0 = (nt >> 7) * 128;
        const int nn0 = (nt & 127) * 128;

        #pragma unroll
        for (int c = 0; c < 8; c++) {
            asm volatile("cp.async.wait_group 0;" ::: "memory");
            __syncthreads();        // publish copies; fence epilogue/goodf
            if (c == 0 && tid < 128) goodf[tid] = (float)g_good[n0 + tid];
            if (c < 7)               load_chunk(m0, n0, c + 1, (c + 1) & 1);
            else if (has_next)       load_chunk(nm0, nn0, 0, 0);

            uint32_t sa = sbase + (c & 1) * STAGE_BYTES;
            uint32_t sb = sa + B_OFF;
            #pragma unroll
            for (int kk = 0; kk < 4; kk++) {
                uint32_t a[2][4];
                #pragma unroll
                for (int mi = 0; mi < 2; mi++) {
                    uint32_t o = (uint32_t)(arow + mi * 16) * 128 +
                                 (kk * 2 + acolh) * 16;
                    ldsm4(a[mi], sa + SWZ(o));
                }
                uint32_t b[8][2];
                #pragma unroll
                for (int nj = 0; nj < 4; nj++) {
                    uint32_t q[4];
                    uint32_t o = (uint32_t)(brow + nj * 16) * 128 +
                                 (kk * 2 + bcolh) * 16;
                    ldsm4(q, sb + SWZ(o));
                    b[2 * nj][0] = q[0]; b[2 * nj][1] = q[1];
                    b[2 * nj + 1][0] = q[2]; b[2 * nj + 1][1] = q[3];
                }
                #pragma unroll
                for (int mi = 0; mi < 2; mi++)
                    #pragma unroll
                    for (int ni = 0; ni < 8; ni++)
                        mma16816(acc[mi][ni], a[mi], b[ni]);
            }
        }

        // per-tile: fold masked exp into rs, reset acc (overlaps next loads)
        #pragma unroll
        for (int mi = 0; mi < 2; mi++) {
            #pragma unroll
            for (int ni = 0; ni < 8; ni++) {
                int col = wn * 64 + ni * 8 + ((lid & 3) << 1);
                float g0 = goodf[col], g1 = goodf[col + 1];
                float* cacc = acc[mi][ni];
                rs[mi * 2 + 0] += g0 * exp2f(fmaf(C_LOG2E, cacc[0], -C_LOG2E))
                                + g1 * exp2f(fmaf(C_LOG2E, cacc[1], -C_LOG2E));
                rs[mi * 2 + 1] += g0 * exp2f(fmaf(C_LOG2E, cacc[2], -C_LOG2E))
                                + g1 * exp2f(fmaf(C_LOG2E, cacc[3], -C_LOG2E));
                cacc[0] = 0.0f; cacc[1] = 0.0f; cacc[2] = 0.0f; cacc[3] = 0.0f;
            }
        }
        // flush rowsums when the M row changes or strip ends
        if (!has_next || nm0 != m0) {
            #pragma unroll
            for (int k = 0; k < 4; k++) {
                rs[k] += __shfl_xor_sync(0xffffffffu, rs[k], 1);
                rs[k] += __shfl_xor_sync(0xffffffffu, rs[k], 2);
            }
            if ((lid & 3) == 0) {
                int r0 = m0 + wm * 32 + (lid >> 2);
                atomicAdd(&g_rowsum[r0 +  0], rs[0]);
                atomicAdd(&g_rowsum[r0 +  8], rs[1]);
                atomicAdd(&g_rowsum[r0 + 16], rs[2]);
                atomicAdd(&g_rowsum[r0 + 24], rs[3]);
            }
            rs[0] = rs[1] = rs[2] = rs[3] = 0.0f;
        }
    }
}

// ---------------- 5: final reduce --------------------------------------------
__global__ void k_final(float* __restrict__ out) {
    int t = threadIdx.x;          // 512
    float s = 0.0f;
    #pragma unroll
    for (int i = 0; i < BB / 512; i++) {
        int b = t + i * 512;
        s += (OIM_SCALE + __logf(g_rowsum[b])) - g_target[b];
    }
    #pragma unroll
    for (int o = 16; o; o >>= 1) s += __shfl_xor_sync(0xffffffffu, s, o);
    __shared__ float sh[16];
    if ((t & 31) == 0) sh[t >> 5] = s;
    __syncthreads();
    if (t == 0) {
        float tot = 0.0f;
        #pragma unroll
        for (int w = 0; w < 16; w++) tot += sh[w];
        out[0] = tot / (float)BB;
    }
}

// ---------------- launch ------------------------------------------------------
extern "C" void kernel_launch(void* const* d_in, const int* in_sizes, int n_in,
                              void* d_out, int out_size) {
    const float* inputs   = (const float*)d_in[0];
    const int*   labels   = (const int*)  d_in[1];
    const float* emb_cq   = (const float*)d_in[2];
    const int*   label_cq = (const int*)  d_in[3];
    const int*   header   = (const int*)  d_in[5];
    float* out = (float*)d_out;

    cudaFuncSetAttribute(k_gemm, cudaFuncAttributeMaxDynamicSharedMemorySize,
                         SMEM_DYN);

    k_row<<<BB / 8, 128>>>(inputs, labels);
    k_class<<<UU, 128>>>();
    k_build<<<QQ / 8 + BB, 128>>>(emb_cq, label_cq, header, labels, inputs);
    k_gemm<<<NCTA, 256, SMEM_DYN>>>();
    k_final<<<1, 512>>>(out);
}

// round 17
// speedup vs baseline: 1.0433x; 1.0433x over previous
#include <cuda_runtime.h>
#include <cuda_bf16.h>
#include <math.h>
#include <stdint.h>

#define BB 4096
#define DD 512
#define QQ 16384
#define UU 256
#define OIM_SCALE 30.0f
#define C_LOG2E 43.280851226668896f   // 30 * log2(e)

// ---------------- scratch (device globals; no allocation allowed) ----------
__device__ float g_cls_sum[UU * DD];              // zeroed by k_gemm prologue
__device__ int   g_cls_cnt[UU];                   // zeroed by k_gemm prologue
__device__ int   g_unrank[UU];
__device__ float g_uniq_emb_n[UU * DD];
__device__ __nv_bfloat16 g_Abf[BB * DD];          // 4 MB (normalized inputs, bf16)
__device__ __nv_bfloat16 g_Bbf[(size_t)QQ * DD];  // 16 MB (effective queue, bf16)
__device__ unsigned char g_good[QQ];
__device__ float g_target[BB];
__device__ float g_rowsum[BB];

// ---------------- helpers ----------------------------------------------------
__device__ __forceinline__ uint32_t smem_u32(const void* p) {
    uint32_t a;
    asm("{ .reg .u64 t; cvta.to.shared.u64 t, %1; cvt.u32.u64 %0, t; }"
        : "=r"(a) : "l"(p));
    return a;
}
__device__ __forceinline__ void cpa16(uint32_t sm, const void* g) {
    asm volatile("cp.async.cg.shared.global [%0], [%1], 16;" :: "r"(sm), "l"(g));
}
__device__ __forceinline__ void cpa_commit() {
    asm volatile("cp.async.commit_group;" ::: "memory");
}
__device__ __forceinline__ void ldsm4(uint32_t* r, uint32_t addr) {
    asm volatile("ldmatrix.sync.aligned.m8n8.x4.shared.b16 {%0,%1,%2,%3}, [%4];"
                 : "=r"(r[0]), "=r"(r[1]), "=r"(r[2]), "=r"(r[3]) : "r"(addr));
}
__device__ __forceinline__ void mma16816(float* d, const uint32_t* a,
                                         const uint32_t* b) {
    asm volatile(
        "mma.sync.aligned.m16n8k16.row.col.f32.bf16.bf16.f32 "
        "{%0,%1,%2,%3}, {%4,%5,%6,%7}, {%8,%9}, {%0,%1,%2,%3};"
        : "+f"(d[0]), "+f"(d[1]), "+f"(d[2]), "+f"(d[3])
        : "r"(a[0]), "r"(a[1]), "r"(a[2]), "r"(a[3]), "r"(b[0]), "r"(b[1]));
}
#define SWZ(o) ((o) ^ (((o) >> 3) & 0x70))

__device__ __forceinline__ void pack_bf16_store(float4 v, __nv_bfloat16* dst,
                                                size_t e) {
    __nv_bfloat162 h01 = __floats2bfloat162_rn(v.x, v.y);
    __nv_bfloat162 h23 = __floats2bfloat162_rn(v.z, v.w);
    uint2 u;
    u.x = *reinterpret_cast<uint32_t*>(&h01);
    u.y = *reinterpret_cast<uint32_t*>(&h23);
    reinterpret_cast<uint2*>(dst)[e >> 2] = u;
}

// ---------------- 1: normalize rows -> bf16 A + scatter (8 rows/block) ------
__global__ void k_row(const float* __restrict__ inputs,
                      const int*   __restrict__ labels) {
    int b0 = blockIdx.x * 8;      // 512 blocks
    int t = threadIdx.x;          // 128
    float4 v[8];
    #pragma unroll
    for (int i = 0; i < 8; i++)
        v[i] = reinterpret_cast<const float4*>(inputs + (size_t)(b0 + i) * DD)[t];
    float s[8];
    #pragma unroll
    for (int i = 0; i < 8; i++)
        s[i] = v[i].x * v[i].x + v[i].y * v[i].y + v[i].z * v[i].z + v[i].w * v[i].w;
    #pragma unroll
    for (int o = 16; o; o >>= 1)
        #pragma unroll
        for (int i = 0; i < 8; i++)
            s[i] += __shfl_xor_sync(0xffffffffu, s[i], o);
    __shared__ float sh[8][4];
    if ((t & 31) == 0)
        #pragma unroll
        for (int i = 0; i < 8; i++) sh[i][t >> 5] = s[i];
    __syncthreads();
    #pragma unroll
    for (int i = 0; i < 8; i++) {
        float inv = 1.0f / fmaxf(sqrtf(sh[i][0] + sh[i][1] + sh[i][2] + sh[i][3]), 1e-12f);
        pack_bf16_store(make_float4(v[i].x * inv, v[i].y * inv, v[i].z * inv, v[i].w * inv),
                        g_Abf, (size_t)(b0 + i) * DD + t * 4);
    }
    #pragma unroll
    for (int i = 0; i < 8; i++) {
        int lab = labels[b0 + i];
        float* cs = g_cls_sum + lab * DD + t * 4;
        atomicAdd(cs + 0, v[i].x); atomicAdd(cs + 1, v[i].y);
        atomicAdd(cs + 2, v[i].z); atomicAdd(cs + 3, v[i].w);
        if (t == 0) atomicAdd(&g_cls_cnt[lab], 1);
    }
}

// ---------------- 2: class means, normalized + rank table --------------------
__global__ void k_class() {
    int u = blockIdx.x;           // 256 blocks
    int t = threadIdx.x;          // 128
    int cnt = g_cls_cnt[u];
    float invc = cnt > 0 ? 1.0f / (float)cnt : 0.0f;
    float4 v = reinterpret_cast<const float4*>(g_cls_sum + u * DD)[t];
    v.x *= invc; v.y *= invc; v.z *= invc; v.w *= invc;
    float ss = v.x * v.x + v.y * v.y + v.z * v.z + v.w * v.w;
    #pragma unroll
    for (int o = 16; o; o >>= 1) ss += __shfl_xor_sync(0xffffffffu, ss, o);
    __shared__ float sh[4];
    __shared__ int shr[4];
    int rloc = 0;
    if (t < u && g_cls_cnt[t] > 0) rloc++;
    if (t + 128 < u && g_cls_cnt[t + 128] > 0) rloc++;
    #pragma unroll
    for (int o = 16; o; o >>= 1) rloc += __shfl_xor_sync(0xffffffffu, rloc, o);
    if ((t & 31) == 0) { sh[t >> 5] = ss; shr[t >> 5] = rloc; }
    __syncthreads();
    float inv = 1.0f / fmaxf(sqrtf(sh[0] + sh[1] + sh[2] + sh[3]), 1e-12f);
    float4 vn = make_float4(v.x * inv, v.y * inv, v.z * inv, v.w * inv);
    reinterpret_cast<float4*>(g_uniq_emb_n + u * DD)[t] = vn;
    if (t == 0 && cnt > 0) {
        int r = shr[0] + shr[1] + shr[2] + shr[3];
        g_unrank[r] = u;
    }
}

// ---------------- 3: fused queue resolution (8 rows, MLP 8) + target logits --
__global__ void k_build(const float* __restrict__ emb_cq,
                        const int*   __restrict__ label_cq,
                        const int*   __restrict__ header,
                        const int*   __restrict__ labels,
                        const float* __restrict__ inputs) {
    int blk = blockIdx.x;
    int t = threadIdx.x;          // 128

    if (blk < QQ / 8) {
        int h0 = header[0];
        int q0 = blk * 8;
        const float* src[8];
        uint64_t gpack = 0;
        #pragma unroll
        for (int i = 0; i < 8; i++) {
            int q = q0 + i;
            int u = q - h0;
            u = ((u % QQ) + QQ) % QQ;
            unsigned char good;
            if (u < UU) {
                src[i] = g_uniq_emb_n + g_unrank[u] * DD;
                good = 1;
            } else {
                int lab = label_cq[q];
                bool inuniq = (lab >= 0 && lab < UU && g_cls_cnt[lab] > 0);
                good = (lab != -1 && !inuniq) ? 1 : 0;
                src[i] = emb_cq + (size_t)q * DD;
            }
            gpack |= (uint64_t)good << (8 * i);
        }
        float4 v[8];
        #pragma unroll
        for (int i = 0; i < 8; i++)
            v[i] = reinterpret_cast<const float4*>(src[i])[t];
        #pragma unroll
        for (int i = 0; i < 8; i++)
            pack_bf16_store(v[i], g_Bbf, (size_t)(q0 + i) * DD + t * 4);
        if (t == 0)
            *reinterpret_cast<uint64_t*>(g_good + q0) = gpack;
    } else {
        int b = blk - QQ / 8;
        int lab = labels[b];
        float4 a = reinterpret_cast<const float4*>(inputs + (size_t)b * DD)[t];
        float4 e = reinterpret_cast<const float4*>(g_uniq_emb_n + lab * DD)[t];
        float ss = a.x * a.x + a.y * a.y + a.z * a.z + a.w * a.w;
        float s  = a.x * e.x + a.y * e.y + a.z * e.z + a.w * e.w;
        #pragma unroll
        for (int o = 16; o; o >>= 1) {
            ss += __shfl_xor_sync(0xffffffffu, ss, o);
            s  += __shfl_xor_sync(0xffffffffu, s, o);
        }
        __shared__ float shs[4], shd[4];
        if ((t & 31) == 0) { shs[t >> 5] = ss; shd[t >> 5] = s; }
        __syncthreads();
        if (t == 0) {
            float tot_ss = shs[0] + shs[1] + shs[2] + shs[3];
            float tot_s  = shd[0] + shd[1] + shd[2] + shd[3];
            float inv = 1.0f / fmaxf(sqrtf(tot_ss), 1e-12f);
            g_target[b] = OIM_SCALE * tot_s * inv;
            g_rowsum[b] = 0.0f;
        }
    }
}

// ---------------- 4: HMMA GEMM + fused masked exp row-sum --------------------
// PROVEN R15 configuration (172.5us): 128x128 tile, 3 cp.async stages,
// 8 warps 4m x 2n, full unroll, single barrier per chunk (wait -> sync ->
// load(c+2) -> compute), occ 2, pipeline fill before prologue housekeeping.
// Converged: all explored perturbations (tile shape, barrier count, stage
// count, wait placement, fused final, persistence) regressed.
#define STAGES 3
#define STAGE_BYTES 32768           // (128+128) rows * 128B
#define B_OFF 16384
#define GOOD_OFF (STAGES * STAGE_BYTES)
#define SMEM_DYN (GOOD_OFF + 512 + 1024)

__global__ void __launch_bounds__(256, 2) k_gemm() {
    extern __shared__ char smraw[];
    const uint32_t sb0 = smem_u32(smraw);
    const uint32_t sbase = (sb0 + 1023) & ~1023u;
    char* smc = smraw + (sbase - sb0);
    float* goodf = (float*)(smc + GOOD_OFF);

    const int tid = threadIdx.x;
    const int lid = tid & 31;
    const int w = tid >> 5;
    const int wm = w >> 1;          // 0..3
    const int wn = w & 1;           // 0..1
    const int n0 = blockIdx.x * 128;
    const int m0 = blockIdx.y * 128;

    const int lrow = tid >> 3;      // 0..31
    const int lch = tid & 7;
    uint32_t soff[4];
    #pragma unroll
    for (int it = 0; it < 4; it++) {
        uint32_t o = (uint32_t)(lrow + it * 32) * 128 + lch * 16;
        soff[it] = SWZ(o);
    }

    auto load_stage = [&](int s, int kc) {
        uint32_t sa = sbase + s * STAGE_BYTES;
        const __nv_bfloat16* gA = g_Abf + (size_t)(m0 + lrow) * DD + kc * 64 + lch * 8;
        const __nv_bfloat16* gB = g_Bbf + (size_t)(n0 + lrow) * DD + kc * 64 + lch * 8;
        #pragma unroll
        for (int it = 0; it < 4; it++) {
            cpa16(sa + soff[it], gA + (size_t)it * 32 * DD);
            cpa16(sa + B_OFF + soff[it], gB + (size_t)it * 32 * DD);
        }
        cpa_commit();
    };

    // pipeline fill first, housekeeping after (copies have no dependence on it)
    load_stage(0, 0);
    load_stage(1, 1);

    // self-cleaning: reset class accumulators for the NEXT graph replay.
    if (blockIdx.y == 0) {
        reinterpret_cast<float4*>(g_cls_sum)[blockIdx.x * 256 + tid] =
            make_float4(0.0f, 0.0f, 0.0f, 0.0f);
        if (blockIdx.x == 0) g_cls_cnt[tid] = 0;
    }
    if (tid < 128) goodf[tid] = (float)g_good[n0 + tid];

    float acc[2][8][4];
    #pragma unroll
    for (int i = 0; i < 2; i++)
        #pragma unroll
        for (int j = 0; j < 8; j++)
            #pragma unroll
            for (int k = 0; k < 4; k++) acc[i][j][k] = 0.0f;

    const int arow = wm * 32 + (lid & 15);
    const int acolh = lid >> 4;
    const int brow = wn * 64 + ((lid >> 4) << 3) + (lid & 7);
    const int bcolh = (lid >> 3) & 1;

    #pragma unroll
    for (int c = 0; c < 8; c++) {
        if (c < 7) asm volatile("cp.async.wait_group 1;" ::: "memory");
        else       asm volatile("cp.async.wait_group 0;" ::: "memory");
        __syncthreads();            // publishes all warps' completed copies
        if (c + 2 < 8) load_stage((c + 2) % STAGES, c + 2);

        uint32_t sa = sbase + (c % STAGES) * STAGE_BYTES;
        uint32_t sb = sa + B_OFF;
        #pragma unroll
        for (int kk = 0; kk < 4; kk++) {
            uint32_t a[2][4];
            #pragma unroll
            for (int mi = 0; mi < 2; mi++) {
                uint32_t o = (uint32_t)(arow + mi * 16) * 128 +
                             (kk * 2 + acolh) * 16;
                ldsm4(a[mi], sa + SWZ(o));
            }
            uint32_t b[8][2];
            #pragma unroll
            for (int nj = 0; nj < 4; nj++) {
                uint32_t q[4];
                uint32_t o = (uint32_t)(brow + nj * 16) * 128 +
                             (kk * 2 + bcolh) * 16;
                ldsm4(q, sb + SWZ(o));
                b[2 * nj][0] = q[0]; b[2 * nj][1] = q[1];
                b[2 * nj + 1][0] = q[2]; b[2 * nj + 1][1] = q[3];
            }
            #pragma unroll
            for (int mi = 0; mi < 2; mi++)
                #pragma unroll
                for (int ni = 0; ni < 8; ni++)
                    mma16816(acc[mi][ni], a[mi], b[ni]);
        }
    }

    // epilogue: masked exp row-sums (exp2 form)
    float rs[4] = {0.0f, 0.0f, 0.0f, 0.0f};
    #pragma unroll
    for (int mi = 0; mi < 2; mi++) {
        #pragma unroll
        for (int ni = 0; ni < 8; ni++) {
            int col = wn * 64 + ni * 8 + ((lid & 3) << 1);
            float g0 = goodf[col], g1 = goodf[col + 1];
            float* cacc = acc[mi][ni];
            rs[mi * 2 + 0] += g0 * exp2f(fmaf(C_LOG2E, cacc[0], -C_LOG2E))
                            + g1 * exp2f(fmaf(C_LOG2E, cacc[1], -C_LOG2E));
            rs[mi * 2 + 1] += g0 * exp2f(fmaf(C_LOG2E, cacc[2], -C_LOG2E))
                            + g1 * exp2f(fmaf(C_LOG2E, cacc[3], -C_LOG2E));
        }
    }
    #pragma unroll
    for (int i = 0; i < 4; i++) {
        rs[i] += __shfl_xor_sync(0xffffffffu, rs[i], 1);
        rs[i] += __shfl_xor_sync(0xffffffffu, rs[i], 2);
    }
    if ((lid & 3) == 0) {
        int r0 = m0 + wm * 32 + (lid >> 2);
        atomicAdd(&g_rowsum[r0 +  0], rs[0]);
        atomicAdd(&g_rowsum[r0 +  8], rs[1]);
        atomicAdd(&g_rowsum[r0 + 16], rs[2]);
        atomicAdd(&g_rowsum[r0 + 24], rs[3]);
    }
}

// ---------------- 5: final reduce --------------------------------------------
__global__ void k_final(float* __restrict__ out) {
    int t = threadIdx.x;          // 512
    float s = 0.0f;
    #pragma unroll
    for (int i = 0; i < BB / 512; i++) {
        int b = t + i * 512;
        s += (OIM_SCALE + __logf(g_rowsum[b])) - g_target[b];
    }
    #pragma unroll
    for (int o = 16; o; o >>= 1) s += __shfl_xor_sync(0xffffffffu, s, o);
    __shared__ float sh[16];
    if ((t & 31) == 0) sh[t >> 5] = s;
    __syncthreads();
    if (t == 0) {
        float tot = 0.0f;
        #pragma unroll
        for (int w = 0; w < 16; w++) tot += sh[w];
        out[0] = tot / (float)BB;
    }
}

// ---------------- launch ------------------------------------------------------
extern "C" void kernel_launch(void* const* d_in, const int* in_sizes, int n_in,
                              void* d_out, int out_size) {
    const float* inputs   = (const float*)d_in[0];
    const int*   labels   = (const int*)  d_in[1];
    const float* emb_cq   = (const float*)d_in[2];
    const int*   label_cq = (const int*)  d_in[3];
    const int*   header   = (const int*)  d_in[5];
    float* out = (float*)d_out;

    cudaFuncSetAttribute(k_gemm, cudaFuncAttributeMaxDynamicSharedMemorySize,
                         SMEM_DYN);

    k_row<<<BB / 8, 128>>>(inputs, labels);
    k_class<<<UU, 128>>>();
    k_build<<<QQ / 8 + BB, 128>>>(emb_cq, label_cq, header, labels, inputs);
    dim3 grid(QQ / 128, BB / 128);
    k_gemm<<<grid, 256, SMEM_DYN>>>();
    k_final<<<1, 512>>>(out);
}